// round 13
// baseline (speedup 1.0000x reference)
#include <cuda_runtime.h>

// Problem constants
#define N_LEN   131072
#define B_ROWS  256

// Tiling: one warp per block; warp owns 512 positions (256 f32x2 position-pairs) of ONE row.
#define TPB     32
#define WTILE   512
#define PAIRS   (WTILE/2)              // 256 pairs per tile
#define HALO_P  16                     // 16 halo pairs = 32 positions
#define W_INP   (PAIRS + HALO_P)       // 272 pair slots
#define W_PAD   ((W_INP/8)*9)          // 306 u64 slots (pad-9-per-8)

typedef unsigned long long u64;

__device__ __forceinline__ u64 pack2(float a, float b) {
    u64 r; asm("mov.b64 %0,{%1,%2};" : "=l"(r) : "f"(a), "f"(b)); return r;
}
__device__ __forceinline__ void unpack2(u64 v, float& a, float& b) {
    asm("mov.b64 {%0,%1},%2;" : "=f"(a), "=f"(b) : "l"(v));
}
__device__ __forceinline__ float lo2(u64 v) { float a, b; unpack2(v, a, b); return a; }
__device__ __forceinline__ float hi2(u64 v) { float a, b; unpack2(v, a, b); return b; }
__device__ __forceinline__ u64 fma2(u64 a, u64 b, u64 c) {
    u64 d; asm("fma.rn.f32x2 %0,%1,%2,%3;" : "=l"(d) : "l"(a), "l"(b), "l"(c)); return d;
}
__device__ __forceinline__ u64 mul2(u64 a, u64 b) {
    u64 d; asm("mul.rn.f32x2 %0,%1,%2;" : "=l"(d) : "l"(a), "l"(b)); return d;
}
__device__ __forceinline__ u64 add2(u64 a, u64 b) {
    u64 d; asm("add.rn.f32x2 %0,%1,%2;" : "=l"(d) : "l"(a), "l"(b)); return d;
}
// shifted pair S[k] = (x[2k-1], x[2k]) from aligned pairs P[k-1], P[k]
__device__ __forceinline__ u64 mkS(u64 prev, u64 cur) { return pack2(hi2(prev), lo2(cur)); }

// pad-9-per-8 swizzle on u64 pair-slots: stride-8 lane patterns -> stride 9 (odd) -> CF
__device__ __forceinline__ int sw9(int k) { return (k >> 3) * 9 + (k & 7); }

__global__ void __launch_bounds__(TPB, 18) fir2(const float* __restrict__ x,
                                                const float* __restrict__ h,
                                                float* __restrict__ y) {
    __shared__ u64 sP[W_PAD];          // x pair-slots: slot k <-> pair (c0/2 - 16 + k)
    __shared__ u64 sHv[8];             // tile-boundary v pairs (positions c0-16..c0-1)

    const int lane = threadIdx.x;
    const int row  = blockIdx.y;
    const int c0   = blockIdx.x * WTILE;
    const float* __restrict__ x0 = x + (size_t)row * N_LEN;
    float* __restrict__ y0 = y + (size_t)row * N_LEN;

    // 16 packed coefficients (h[j],h[j]); pass 2 indexes them reversed
    u64 gph[16];
#pragma unroll
    for (int j = 0; j < 16; j++) { float hv = __ldg(h + j); gph[j] = pack2(hv, hv); }

    // ---- stage x window (544 floats): LDG.128 -> 2x STS.64 (halves are already pairs) ----
#pragma unroll
    for (int it = 0; it < 5; it++) {
        int g = lane + it * 32;                    // float4 group, 136 groups
        if (g < 136) {
            int fg = c0 - 32 + 4 * g;              // global float index; <0 only tile 0
            float4 a;
            if (fg >= 0) a = *reinterpret_cast<const float4*>(x0 + fg);
            else         a = make_float4(0.f, 0.f, 0.f, 0.f);
            int s0 = sw9(2 * g);                   // pairs 2g, 2g+1 adjacent in group
            sP[s0]     = pack2(a.x, a.y);
            sP[s0 + 1] = pack2(a.z, a.w);
        }
    }
    __syncwarp(0xffffffffu);

    const int lp   = 8 * lane;                     // local pair base
    const bool kill = (c0 == 0) && (lane == 0);    // positions 0..15 masked to 0

    // ---- pass 1: V[q] = P[q] + sum_a h2[2a]*S[q-a] + sum_a h2[2a+1]*P[q-1-a] ----
    u64 vbuf[8];
    {
        u64 rP[8], rS[8];
        const int rA = 9 * (lane + 1);             // sw9(lp+8+s) = 9(lane+1)+s
#pragma unroll
        for (int s = 0; s < 8; s++) rP[s] = sP[rA + s];          // P[g0-8+s]
#pragma unroll
        for (int m = 1; m < 8; m++) rS[m] = mkS(rP[m - 1], rP[m]); // S[g0-8+m]

        const int xA = 9 * (lane + 2);             // sw9(lp+16+i) = 9(lane+2)+i
#pragma unroll
        for (int i = 0; i < 8; i++) {
            u64 Pi = sP[xA + i];                   // P[g0+i]
            u64 Si = mkS(rP[(i + 7) & 7], Pi);     // S[g0+i]
            u64 acc0 = fma2(gph[0], Si, Pi);       // identity + even tap a=0
#pragma unroll
            for (int a = 1; a < 8; a++)
                acc0 = fma2(gph[2 * a], rS[(i - a) & 7], acc0);
            u64 acc1 = mul2(gph[1], rP[(i + 7) & 7]);
#pragma unroll
            for (int a = 1; a < 8; a++)
                acc1 = fma2(gph[2 * a + 1], rP[(i - 1 - a) & 7], acc1);
            vbuf[i] = add2(acc0, acc1);
            rP[i & 7] = Pi;
            rS[i & 7] = Si;
        }
    }
    if (kill) {
#pragma unroll
        for (int i = 0; i < 8; i++) vbuf[i] = 0ULL;
    }

    // ---- tile-boundary v halo: lanes 0..7 each recompute one v-pair from x ----
    if (lane < 8) {
        u64 v = 0ULL;
        if (c0 != 0) {                             // c0==0: those positions are masked
            u64 pm[9];                             // pm[a] = P[q-a], q = cp-8+d, slot d+8-a
#pragma unroll
            for (int a = 0; a < 9; a++) pm[a] = sP[sw9(lane + 8 - a)];
            u64 acc0 = fma2(gph[0], mkS(pm[1], pm[0]), pm[0]);
#pragma unroll
            for (int a = 1; a < 8; a++)
                acc0 = fma2(gph[2 * a], mkS(pm[a + 1], pm[a]), acc0);
            u64 acc1 = mul2(gph[1], pm[1]);
#pragma unroll
            for (int a = 1; a < 8; a++)
                acc1 = fma2(gph[2 * a + 1], pm[a + 1], acc1);
            v = add2(acc0, acc1);
        }
        sHv[lane] = v;
    }
    __syncwarp(0xffffffffu);

    // ---- pass 2: Y[q] = V[q] + sum_a g'[2a]*Sv[q-a] + sum_a g'[2a+1]*Av[q-1-a],
    //      g'[j] = gph[15-j]; halo ring via shfl of vbuf ----
    {
        u64 rAv[8], rSv[8];
#pragma unroll
        for (int s = 0; s < 8; s++)
            rAv[s] = __shfl_up_sync(0xffffffffu, vbuf[s], 1);    // prev lane's v-pairs
        if (lane == 0) {
#pragma unroll
            for (int s = 0; s < 8; s++) rAv[s] = sHv[s];
        }
#pragma unroll
        for (int m = 1; m < 8; m++) rSv[m] = mkS(rAv[m - 1], rAv[m]);

#pragma unroll
        for (int i = 0; i < 8; i++) {
            u64 Vi = vbuf[i];
            u64 Svi = mkS(rAv[(i + 7) & 7], Vi);
            u64 acc0 = fma2(gph[15], Svi, Vi);
#pragma unroll
            for (int a = 1; a < 8; a++)
                acc0 = fma2(gph[15 - 2 * a], rSv[(i - a) & 7], acc0);
            u64 acc1 = mul2(gph[14], rAv[(i + 7) & 7]);
#pragma unroll
            for (int a = 1; a < 8; a++)
                acc1 = fma2(gph[14 - 2 * a], rAv[(i - 1 - a) & 7], acc1);
            u64 yv = add2(acc0, acc1);
            if (kill) yv = 0ULL;                   // positions 0..15 masked
            rAv[i & 7] = Vi;
            rSv[i & 7] = Svi;
            vbuf[i] = yv;                          // reuse vbuf as y buffer
        }
    }

    // ---- writeout: direct STG.128, lane-contiguous (16 floats per lane) ----
    {
        float* yp = y0 + c0 + 16 * lane;
#pragma unroll
        for (int t = 0; t < 4; t++) {
            float a0, a1, a2, a3;
            unpack2(vbuf[2 * t],     a0, a1);
            unpack2(vbuf[2 * t + 1], a2, a3);
            *reinterpret_cast<float4*>(yp + 4 * t) = make_float4(a0, a1, a2, a3);
        }
    }
}

extern "C" void kernel_launch(void* const* d_in, const int* in_sizes, int n_in,
                              void* d_out, int out_size) {
    (void)in_sizes; (void)n_in; (void)out_size;
    const float* x = (const float*)d_in[0];
    const float* h = (const float*)d_in[1];
    float* y = (float*)d_out;

    dim3 grid(N_LEN / WTILE, B_ROWS, 1);
    fir2<<<grid, TPB>>>(x, h, y);
}

// round 14
// speedup vs baseline: 1.9065x; 1.9065x over previous
#include <cuda_runtime.h>

// Problem constants
#define N_LEN   131072
#define B_ROWS  256

// Tiling: ONE WARP PER BLOCK; each warp owns a 512-position tile of a row-pair.
#define TPB     32
#define WTILE   512                    // positions per warp tile
#define EPT     16                     // positions per lane
#define W_IN    (WTILE + 32)           // 544 x-pairs incl 32-halo
#define W_PAD   ((W_IN / 16) * 18)     // 612 u64 slots (pad-18: even stride, 16B-aligned)

typedef unsigned long long u64;

__device__ __forceinline__ u64 pack2(float a, float b) {
    u64 r; asm("mov.b64 %0,{%1,%2};" : "=l"(r) : "f"(a), "f"(b)); return r;
}
__device__ __forceinline__ void unpack2(u64 v, float& a, float& b) {
    asm("mov.b64 {%0,%1},%2;" : "=f"(a), "=f"(b) : "l"(v));
}
__device__ __forceinline__ u64 fma2(u64 a, u64 b, u64 c) {
    u64 d; asm("fma.rn.f32x2 %0,%1,%2,%3;" : "=l"(d) : "l"(a), "l"(b), "l"(c)); return d;
}
__device__ __forceinline__ u64 mul2(u64 a, u64 b) {
    u64 d; asm("mul.rn.f32x2 %0,%1,%2;" : "=l"(d) : "l"(a), "l"(b)); return d;
}
__device__ __forceinline__ u64 add2(u64 a, u64 b) {
    u64 d; asm("add.rn.f32x2 %0,%1,%2;" : "=l"(d) : "l"(a), "l"(b)); return d;
}

// pad-18-per-16 swizzle: lane stride 18 slots = 36 words == 4 mod 32 ->
// 8-lane LDS.128 wavefronts hit distinct 4-word bank groups (conflict-free),
// and all lane bases are even -> 16B alignment for 128-bit smem ops.
__device__ __forceinline__ int sw(int k) { return (k >> 4) * 18 + (k & 15); }

__global__ void __launch_bounds__(TPB, 16) fir2(const float* __restrict__ x,
                                                const float* __restrict__ h,
                                                float* __restrict__ y) {
    __shared__ __align__(16) u64 sIn[W_PAD];   // x window; reused for y staging
    __shared__ u64 sHv[16];                    // tile-boundary v halo

    const int lane = threadIdx.x;
    const int pair = blockIdx.y;
    const int c0   = blockIdx.x * WTILE;               // warp tile base
    const float* __restrict__ x0 = x + (size_t)(2 * pair) * N_LEN;
    const float* __restrict__ x1 = x0 + N_LEN;
    float* __restrict__ y0 = y + (size_t)(2 * pair) * N_LEN;
    float* __restrict__ y1 = y0 + N_LEN;

    // 16 packed coefficients via 4x LDG.128; pass 2 indexes reversed as h[15-j]
    u64 gph[16];
    {
        const float4* h4 = reinterpret_cast<const float4*>(h);
#pragma unroll
        for (int q = 0; q < 4; q++) {
            float4 hv = __ldg(h4 + q);
            gph[4 * q + 0] = pack2(hv.x, hv.x);
            gph[4 * q + 1] = pack2(hv.y, hv.y);
            gph[4 * q + 2] = pack2(hv.z, hv.z);
            gph[4 * q + 3] = pack2(hv.w, hv.w);
        }
    }

    // ---- stage x: LDG.128 both rows -> 2x STS.128 (pair-interleaved float4) ----
#pragma unroll
    for (int it = 0; it < 5; it++) {
        int g = lane + it * 32;        // float4 group, 136 groups of 4 pairs
        if (g < W_IN / 4) {
            int p = c0 - 32 + 4 * g;   // 16B-aligned; <0 only for the first tile
            float4 a0, a1;
            if (p >= 0) {
                a0 = *reinterpret_cast<const float4*>(x0 + p);
                a1 = *reinterpret_cast<const float4*>(x1 + p);
            } else {
                a0 = make_float4(0.f, 0.f, 0.f, 0.f);
                a1 = make_float4(0.f, 0.f, 0.f, 0.f);
            }
            int s0 = sw(4 * g);        // even slot -> 16B aligned
            *reinterpret_cast<float4*>(&sIn[s0])     = make_float4(a0.x, a1.x, a0.y, a1.y);
            *reinterpret_cast<float4*>(&sIn[s0 + 2]) = make_float4(a0.z, a1.z, a0.w, a1.w);
        }
    }
    __syncwarp(0xffffffffu);

    const bool kill = (c0 == 0) && (lane == 0);        // positions 0..15 masked to 0

    // ---- pass 1: v[p] = x[p] + sum_{j=0..15} h[j]*x[p-1-j]; kept in regs ----
    u64 vbuf[16];
    {
        u64 r[16];                     // x ring: local pos q at slot q&15
        const int rA = 18 * (lane + 1);                // slots rA..rA+15 = x[c0+lo-16..]
#pragma unroll
        for (int m = 0; m < 8; m++) {
            ulonglong2 w = *reinterpret_cast<const ulonglong2*>(&sIn[rA + 2 * m]);
            r[2 * m] = w.x; r[2 * m + 1] = w.y;
        }

        const int xA = 18 * (lane + 2);                // slots xA+t = x[c0+lo+t]
#pragma unroll
        for (int t2 = 0; t2 < 8; t2++) {
            ulonglong2 X = *reinterpret_cast<const ulonglong2*>(&sIn[xA + 2 * t2]);
#pragma unroll
            for (int half = 0; half < 2; half++) {
                const int t = 2 * t2 + half;
                u64 xi = half ? X.y : X.x;
                u64 acc0 = xi;
#pragma unroll
                for (int j = 0; j < 8; j++)
                    acc0 = fma2(gph[j], r[(t + 15 - j) & 15], acc0);
                u64 acc1 = mul2(gph[8], r[(t + 7) & 15]);
#pragma unroll
                for (int j = 9; j < 16; j++)
                    acc1 = fma2(gph[j], r[(t + 15 - j) & 15], acc1);
                vbuf[t] = add2(acc0, acc1);
                r[t & 15] = xi;
            }
        }
    }
    if (kill) {
#pragma unroll
        for (int t = 0; t < EPT; t++) vbuf[t] = 0ULL;
    }

    // ---- tile-boundary v halo: v[c0-16+s] recomputed from x (lanes 0..15) ----
    if (lane < 16) {
        u64 v = 0ULL;
        if (c0 - 16 + lane >= 16) {                    // pos>=16 -> unmasked
            u64 xi = sIn[sw(16 + lane)];               // x[c0-16+lane]
            u64 a0 = xi;
#pragma unroll
            for (int j = 0; j < 8; j++)  a0 = fma2(gph[j], sIn[sw(15 + lane - j)], a0);
            u64 a1 = mul2(gph[8], sIn[sw(7 + lane)]);
#pragma unroll
            for (int j = 9; j < 16; j++) a1 = fma2(gph[j], sIn[sw(15 + lane - j)], a1);
            v = add2(a0, a1);
        }
        sHv[lane] = v;
    }
    __syncwarp(0xffffffffu);           // sHv visible; all x reads done before y overwrites

    // ---- pass 2: y[p] = v[p] + sum_j h[15-j]*v[p-1-j]; halo via shfl ----
    {
        u64 hv[16];                    // v[lo-16+s]: previous lane's vbuf
#pragma unroll
        for (int s = 0; s < 16; s++)
            hv[s] = __shfl_up_sync(0xffffffffu, vbuf[s], 1);
        if (lane == 0) {
#pragma unroll
            for (int s = 0; s < 16; s++) hv[s] = sHv[s];
        }

        const int yA = 18 * lane;      // slot sw(lo+t) = 18*lane + t (even base)
        u64 ysave = 0ULL;
#pragma unroll
        for (int t = 0; t < EPT; t++) {
            u64 acc0 = vbuf[t];
#pragma unroll
            for (int j = 0; j < 8; j++) {
                int k = t - 1 - j;
                u64 tap = (k >= 0) ? vbuf[k] : hv[16 + k];
                acc0 = fma2(gph[15 - j], tap, acc0);
            }
            u64 tap8;
            { int k = t - 9; tap8 = (k >= 0) ? vbuf[k] : hv[16 + k]; }
            u64 acc1 = mul2(gph[7], tap8);
#pragma unroll
            for (int j = 9; j < 16; j++) {
                int k = t - 1 - j;
                u64 tap = (k >= 0) ? vbuf[k] : hv[16 + k];
                acc1 = fma2(gph[15 - j], tap, acc1);
            }
            u64 yv = add2(acc0, acc1);
            if (kill) yv = 0ULL;       // positions 0..15 masked
            if (t & 1) {               // paired STS.128 (16B-aligned even base)
                ulonglong2 w; w.x = ysave; w.y = yv;
                *reinterpret_cast<ulonglong2*>(&sIn[yA + t - 1]) = w;
            } else {
                ysave = yv;
            }
        }
    }
    __syncwarp(0xffffffffu);           // y staged

    // ---- writeout: LDS.128 gathers + coalesced STG.128 per row ----
#pragma unroll
    for (int it = 0; it < 4; it++) {
        int fi = 4 * (lane + it * 32); // 4-pair group
        int ix = sw(fi);               // even slot, 16B aligned
        ulonglong2 p0 = *reinterpret_cast<const ulonglong2*>(&sIn[ix]);
        ulonglong2 p1 = *reinterpret_cast<const ulonglong2*>(&sIn[ix + 2]);
        float a[4], b[4];
        unpack2(p0.x, a[0], b[0]); unpack2(p0.y, a[1], b[1]);
        unpack2(p1.x, a[2], b[2]); unpack2(p1.y, a[3], b[3]);
        *reinterpret_cast<float4*>(y0 + c0 + fi) = make_float4(a[0], a[1], a[2], a[3]);
        *reinterpret_cast<float4*>(y1 + c0 + fi) = make_float4(b[0], b[1], b[2], b[3]);
    }
}

extern "C" void kernel_launch(void* const* d_in, const int* in_sizes, int n_in,
                              void* d_out, int out_size) {
    (void)in_sizes; (void)n_in; (void)out_size;
    const float* x = (const float*)d_in[0];
    const float* h = (const float*)d_in[1];
    float* y = (float*)d_out;

    dim3 grid(N_LEN / WTILE, B_ROWS / 2, 1);
    fir2<<<grid, TPB>>>(x, h, y);
}